// round 12
// baseline (speedup 1.0000x reference)
#include <cuda_runtime.h>

// RegionPartitioner, band-aligned write-once, 2x2 footprint per thread.
// out[b, r, c, i, j] = x[b, c, min(ri*32+i, 499), min(rj*32+j, 499)],
//   r = ri*15 + rj, 15x15 regions of 64x64, step 32.
// Output: (8, 225, 4, 64, 64) fp32.
//
// One thread owns a 32B column chunk (2 adjacent float4) x two rows (tr,
// tr+16) of one 32x32 input band: 4 LDG.128 (MLP=4) + 16 STG.128, with the
// 4 region base addresses computed once and reused via constant offsets.
// Every output element written exactly once; edge replication via load-time
// clamping. Each warp sits in one (row-band, col-band) -> warp-uniform
// store bounds, dense 128B store runs (lesson from R9).

namespace {
constexpr int B  = 8;
constexpr int C  = 4;
constexpr int H  = 500;
constexpr int W  = 500;
constexpr int RS = 64;
constexpr int NR = 15;
constexpr int R  = NR * NR;     // 225
}  // namespace

__global__ __launch_bounds__(256)
void region_partition_kernel(const float* __restrict__ x,
                             float4* __restrict__ out) {
    const int blk = blockIdx.x;             // 0..63
    const int rbq = blk >> 4;               // row-band quad 0..3
    const int cb  = blk & 15;               // col band 0..15
    const int bc  = blockIdx.y;             // 0..31
    const int b   = bc >> 2;
    const int c   = bc & 3;

    const int t   = threadIdx.x;            // 0..255
    const int rb  = (rbq << 2) | (t >> 6);  // row band 0..15; warp-uniform
    const int th  = t & 63;                 // thread within band group
    const int tcp = th & 3;                 // 32B column chunk (4 x 32B = 32 cols)
    const int tr  = th >> 2;                // 0..15 -> rows tr and tr+16

    // ---- Load 2 rows x 2 float4 (clamped at edges). ----
    const int row0 = rb * 32 + tr;
    const int rA   = min(row0,      H - 1);
    const int rBo  = min(row0 + 16, H - 1); // rb==15, tr>=4 clamps to 499
    const int col0 = cb * 32 + tcp * 8;
    const float* srcb = x + (long long)bc * H * W;
    const float* p0 = srcb + rA  * W;
    const float* p1 = srcb + rBo * W;

    float4 v00, v01, v10, v11;
    if (col0 + 7 <= W - 1) {
        v00 = *reinterpret_cast<const float4*>(p0 + col0);
        v01 = *reinterpret_cast<const float4*>(p0 + col0 + 4);
        v10 = *reinterpret_cast<const float4*>(p1 + col0);
        v11 = *reinterpret_cast<const float4*>(p1 + col0 + 4);
    } else {                                // cb==15, tcp>=2: cols >= 496
        const int c0 = min(col0,     W - 1), c1 = min(col0 + 1, W - 1);
        const int c2 = min(col0 + 2, W - 1), c3 = min(col0 + 3, W - 1);
        const int c4 = min(col0 + 4, W - 1), c5 = min(col0 + 5, W - 1);
        const int c6 = min(col0 + 6, W - 1), c7 = min(col0 + 7, W - 1);
        v00.x = p0[c0]; v00.y = p0[c1]; v00.z = p0[c2]; v00.w = p0[c3];
        v01.x = p0[c4]; v01.y = p0[c5]; v01.z = p0[c6]; v01.w = p0[c7];
        v10.x = p1[c0]; v10.y = p1[c1]; v10.z = p1[c2]; v10.w = p1[c3];
        v11.x = p1[c4]; v11.y = p1[c5]; v11.z = p1[c6]; v11.w = p1[c7];
    }

    // ---- Target regions (warp-uniform branches). ----
    int ris[2], iis[2], nri = 0;
    if (rb >= 1)      { ris[nri] = rb - 1; iis[nri] = 32 + tr;      nri++; }
    if (rb <= NR - 1) { ris[nri] = rb;     iis[nri] = tr;           nri++; }
    int rjs[2], jjs[2], nrj = 0;
    if (cb >= 1)      { rjs[nrj] = cb - 1; jjs[nrj] = 8 + 2 * tcp;  nrj++; }
    if (cb <= NR - 1) { rjs[nrj] = cb;     jjs[nrj] = 2 * tcp;      nrj++; }

    // Stores: per (a,d), one base; 4 float4 at constant offsets.
#pragma unroll
    for (int a = 0; a < 2; a++) {
        if (a >= nri) break;
#pragma unroll
        for (int d = 0; d < 2; d++) {
            if (d >= nrj) break;
            float4* dst = out +
                (((long long)(b * R + ris[a] * NR + rjs[d]) * C + c) * RS +
                 iis[a]) * (RS / 4) + jjs[d];
            dst[0]           = v00;
            dst[1]           = v01;
            dst[16 * 16]     = v10;      // +16 region rows = +256 float4
            dst[16 * 16 + 1] = v11;
        }
    }
}

extern "C" void kernel_launch(void* const* d_in, const int* in_sizes, int n_in,
                              void* d_out, int out_size) {
    const float* x = (const float*)d_in[0];
    float4* out = (float4*)d_out;

    dim3 grid(4 * 16, B * C);   // (64, 32) = 2048 blocks, 524K threads
    region_partition_kernel<<<grid, 256>>>(x, out);
}

// round 13
// speedup vs baseline: 1.4251x; 1.4251x over previous
#include <cuda_runtime.h>

// RegionPartitioner, band-aligned write-once, 2-rows-per-thread (R10 layout)
// + evict-first (__stcs) stores. Single-variable A/B vs R10.
// out[b, r, c, i, j] = x[b, c, min(ri*32+i, 499), min(rj*32+j, 499)],
//   r = ri*15 + rj, 15x15 regions of 64x64, step 32.
// Output: (8, 225, 4, 64, 64) fp32.
//
// One thread owns a 16B column-chunk of TWO rows (tr, tr+16) of one 32x32
// input band. 2 LDG.128 (MLP=2) + 8 STG.128; 4 region base addresses
// computed once, second row reuses them at +256 float4. Warp store shape:
// 8 lanes per row-run -> dense 128B runs (R9/R11 lesson). Every output
// element written exactly once; edge replication via load-time clamping.
// __stcs marks output lines evict-first so the 118MB write-once stream
// doesn't occupy L2 against the input working set.

namespace {
constexpr int B  = 8;
constexpr int C  = 4;
constexpr int H  = 500;
constexpr int W  = 500;
constexpr int RS = 64;
constexpr int NR = 15;
constexpr int R  = NR * NR;     // 225
}  // namespace

__global__ __launch_bounds__(256)
void region_partition_kernel(const float* __restrict__ x,
                             float4* __restrict__ out) {
    const int blk = blockIdx.x;            // 0..127
    const int rbp = blk >> 4;              // row-band pair 0..7
    const int cb  = blk & 15;              // col band 0..15
    const int bc  = blockIdx.y;            // 0..31
    const int b   = bc >> 2;
    const int c   = bc & 3;

    const int t   = threadIdx.x;           // 0..255
    const int rb  = (rbp << 1) | (t >> 7); // row band; warp-uniform (half split)
    const int th  = t & 127;               // thread within band-half
    const int tc  = th & 7;                // 16B column chunk (8 x 16B = 32 cols)
    const int tr  = th >> 3;               // 0..15 -> rows tr and tr+16

    // ---- Load two rows of this thread's 16B chunk (clamped at edges). ----
    const int row0 = rb * 32 + tr;
    const int rA   = min(row0,      H - 1);
    const int row1 = min(row0 + 16, H - 1);   // rb==15, tr>=4 clamps to 499
    const int col0 = cb * 32 + tc * 4;
    const float* srcb = x + (long long)bc * H * W;
    const float* p0 = srcb + rA   * W;
    const float* p1 = srcb + row1 * W;

    float4 v0, v1;
    if (col0 + 3 <= W - 1) {
        v0 = *reinterpret_cast<const float4*>(p0 + col0);
        v1 = *reinterpret_cast<const float4*>(p1 + col0);
    } else {                               // cb==15, tc>=5: cols >= 500
        const int c0 = min(col0,     W - 1);
        const int c1 = min(col0 + 1, W - 1);
        const int c2 = min(col0 + 2, W - 1);
        const int c3 = min(col0 + 3, W - 1);
        v0.x = p0[c0]; v0.y = p0[c1]; v0.z = p0[c2]; v0.w = p0[c3];
        v1.x = p1[c0]; v1.y = p1[c1]; v1.z = p1[c2]; v1.w = p1[c3];
    }

    // ---- Target regions (warp-uniform branches). ----
    int ris[2], iis[2], nri = 0;
    if (rb >= 1)      { ris[nri] = rb - 1; iis[nri] = 32 + tr; nri++; }
    if (rb <= NR - 1) { ris[nri] = rb;     iis[nri] = tr;      nri++; }
    int rjs[2], jjs[2], nrj = 0;
    if (cb >= 1)      { rjs[nrj] = cb - 1; jjs[nrj] = 8 + tc;  nrj++; }
    if (cb <= NR - 1) { rjs[nrj] = cb;     jjs[nrj] = tc;      nrj++; }

    // Stores: per (a,d), one base address; row tr -> base, row tr+16 -> +256.
    // For fixed (a,d,row), 8 consecutive tc write a contiguous 128B run.
#pragma unroll
    for (int a = 0; a < 2; a++) {
        if (a >= nri) break;
#pragma unroll
        for (int d = 0; d < 2; d++) {
            if (d >= nrj) break;
            float4* dst = out +
                (((long long)(b * R + ris[a] * NR + rjs[d]) * C + c) * RS +
                 iis[a]) * (RS / 4) + jjs[d];
            __stcs(dst,           v0);
            __stcs(dst + 16 * 16, v1);    // +16 region rows = +256 float4
        }
    }
}

extern "C" void kernel_launch(void* const* d_in, const int* in_sizes, int n_in,
                              void* d_out, int out_size) {
    const float* x = (const float*)d_in[0];
    float4* out = (float4*)d_out;

    dim3 grid(8 * 16, B * C);   // (128, 32) = 4096 blocks, 1.05M threads
    region_partition_kernel<<<grid, 256>>>(x, out);
}